// round 1
// baseline (speedup 1.0000x reference)
#include <cuda_runtime.h>

#define T_LEN 2048
#define E_N   19
#define B_N   64
#define H_N   32

typedef unsigned long long u64;

// final hidden states: [b][e][dir][l] -> ((b*E + e)*2 + d)*H + l
__device__ float g_hfinal[B_N * E_N * 2 * H_N];

__device__ __forceinline__ u64 ffma2(u64 a, u64 b, u64 c) {
    u64 d;
    asm("fma.rn.f32x2 %0, %1, %2, %3;" : "=l"(d) : "l"(a), "l"(b), "l"(c));
    return d;
}
__device__ __forceinline__ u64 pack2(float lo, float hi) {
    u64 r;
    asm("mov.b64 %0, {%1, %2};" : "=l"(r) : "f"(lo), "f"(hi));
    return r;
}
__device__ __forceinline__ void unpack2(u64 v, float &lo, float &hi) {
    asm("mov.b64 {%0, %1}, %2;" : "=f"(lo), "=f"(hi) : "l"(v));
}

// sigmoid(x) = 1/(1+2^(-x*log2e)), rcp refined with one Newton step (~1e-7 rel err)
__device__ __forceinline__ float fast_sigmoid(float x) {
    float e, r;
    asm("ex2.approx.f32 %0, %1;" : "=f"(e) : "f"(x * -1.4426950408889634f));
    float dd = 1.0f + e;
    asm("rcp.approx.f32 %0, %1;" : "=f"(r) : "f"(dd));
    r = fmaf(r, fmaf(-dd, r, 1.0f), r);
    return r;
}
// tanh(x) = 2*sigmoid(2x) - 1
__device__ __forceinline__ float fast_tanh(float x) {
    float e, r;
    asm("ex2.approx.f32 %0, %1;" : "=f"(e) : "f"(x * -2.8853900817779268f));
    float dd = 1.0f + e;
    asm("rcp.approx.f32 %0, %1;" : "=f"(r) : "f"(dd));
    r = fmaf(r, fmaf(-dd, r, 1.0f), r);
    return fmaf(2.0f, r, -1.0f);
}

// One warp per (electrode, direction, batch-pair). Lane l owns hidden unit l.
// W_hh lives in registers packed f32x2 as (Wi,Wf) and (Wg,Wo) pairs.
// h state exchanged via duplicated-pair smem ring (broadcast LDS), warp-local sync only.
__global__ void __launch_bounds__(32)
lstm_kernel(const float* __restrict__ x,      // [B, T, E]
            const float* __restrict__ w_ih,   // [E, 2, 4H]
            const float* __restrict__ w_hh,   // [E, 2, 4H, H]
            const float* __restrict__ b_ih,   // [E, 2, 4H]
            const float* __restrict__ b_hh)   // [E, 2, 4H]
{
    __shared__ ulonglong2 hbuf[2][2][H_N / 2];   // [buffer][batch][h-pair], dup-packed
    const int lane = threadIdx.x;
    const int bid  = blockIdx.x;
    const int bp   = bid & 31;     // batch pair 0..31
    const int ed   = bid >> 5;     // 0..37 = e*2 + d
    const int e    = ed >> 1;
    const int d    = ed & 1;
    const int b0   = bp * 2;

    // ---- load recurrent weights into registers, gate-pair packed ----
    // gate rows for hidden-out index `lane`: i=lane, f=32+lane, g=64+lane, o=96+lane
    const float* Wrow = w_hh + (ed * 4 * H_N + lane) * H_N;
    u64 Wif[H_N], Wgo[H_N];
#pragma unroll
    for (int j = 0; j < H_N / 4; j++) {
        float4 wi = *(const float4*)(Wrow + 0 * H_N * H_N + 4 * j);
        float4 wf = *(const float4*)(Wrow + 1 * H_N * H_N + 4 * j);
        float4 wg = *(const float4*)(Wrow + 2 * H_N * H_N + 4 * j);
        float4 wo = *(const float4*)(Wrow + 3 * H_N * H_N + 4 * j);
        Wif[4*j+0] = pack2(wi.x, wf.x);  Wgo[4*j+0] = pack2(wg.x, wo.x);
        Wif[4*j+1] = pack2(wi.y, wf.y);  Wgo[4*j+1] = pack2(wg.y, wo.y);
        Wif[4*j+2] = pack2(wi.z, wf.z);  Wgo[4*j+2] = pack2(wg.z, wo.z);
        Wif[4*j+3] = pack2(wi.w, wf.w);  Wgo[4*j+3] = pack2(wg.w, wo.w);
    }

    const int gb = ed * 4 * H_N + lane;
    const u64 bias_if = pack2(b_ih[gb]           + b_hh[gb],
                              b_ih[gb +     H_N] + b_hh[gb +     H_N]);
    const u64 bias_go = pack2(b_ih[gb + 2 * H_N] + b_hh[gb + 2 * H_N],
                              b_ih[gb + 3 * H_N] + b_hh[gb + 3 * H_N]);
    const u64 wih_if  = pack2(w_ih[gb],           w_ih[gb +     H_N]);
    const u64 wih_go  = pack2(w_ih[gb + 2 * H_N], w_ih[gb + 3 * H_N]);

    ((u64*)&hbuf[0][0][0])[lane] = 0ull;
    ((u64*)&hbuf[0][1][0])[lane] = 0ull;
    float c0 = 0.f, c1 = 0.f, h0v = 0.f, h1v = 0.f;
    __syncwarp();

    // direction 0: t = 0..T-1 forward; direction 1: t = T-1..0
    const int tstart = d ? (T_LEN - 1) : 0;
    const int stride = d ? -E_N : E_N;
    const float* xp0 = x + ((long long)b0 * T_LEN + tstart) * E_N + e;
    const float* xp1 = xp0 + (long long)T_LEN * E_N;

    float x0 = __ldg(xp0);
    float x1 = __ldg(xp1);
    int cur = 0;

#pragma unroll 1
    for (int t = 0; t < T_LEN; t++) {
        // prefetch next step's scalar inputs (broadcast LDG, hidden under FMAs)
        if (t < T_LEN - 1) { xp0 += stride; xp1 += stride; }
        const float x0n = __ldg(xp0);
        const float x1n = __ldg(xp1);

        u64 xd0 = pack2(x0, x0), xd1 = pack2(x1, x1);
        u64 aif0 = ffma2(xd0, wih_if, bias_if);
        u64 ago0 = ffma2(xd0, wih_go, bias_go);
        u64 aif1 = ffma2(xd1, wih_if, bias_if);
        u64 ago1 = ffma2(xd1, wih_go, bias_go);

        const ulonglong2* hb0 = hbuf[cur][0];
        const ulonglong2* hb1 = hbuf[cur][1];
#pragma unroll
        for (int j = 0; j < H_N / 2; j++) {
            ulonglong2 hh0 = hb0[j];   // broadcast LDS.128: two dup-packed h values
            ulonglong2 hh1 = hb1[j];
            aif0 = ffma2(Wif[2*j],     hh0.x, aif0);
            ago0 = ffma2(Wgo[2*j],     hh0.x, ago0);
            aif1 = ffma2(Wif[2*j],     hh1.x, aif1);
            ago1 = ffma2(Wgo[2*j],     hh1.x, ago1);
            aif0 = ffma2(Wif[2*j+1],   hh0.y, aif0);
            ago0 = ffma2(Wgo[2*j+1],   hh0.y, ago0);
            aif1 = ffma2(Wif[2*j+1],   hh1.y, aif1);
            ago1 = ffma2(Wgo[2*j+1],   hh1.y, ago1);
        }

        float gi, gf, gg, go;
        unpack2(aif0, gi, gf); unpack2(ago0, gg, go);
        {
            float si = fast_sigmoid(gi), sf = fast_sigmoid(gf);
            float tg = fast_tanh(gg),    so = fast_sigmoid(go);
            c0  = fmaf(sf, c0, si * tg);
            h0v = so * fast_tanh(c0);
        }
        unpack2(aif1, gi, gf); unpack2(ago1, gg, go);
        {
            float si = fast_sigmoid(gi), sf = fast_sigmoid(gf);
            float tg = fast_tanh(gg),    so = fast_sigmoid(go);
            c1  = fmaf(sf, c1, si * tg);
            h1v = so * fast_tanh(c1);
        }

        const int nxt = cur ^ 1;
        ((u64*)&hbuf[nxt][0][0])[lane] = pack2(h0v, h0v);
        ((u64*)&hbuf[nxt][1][0])[lane] = pack2(h1v, h1v);
        __syncwarp();
        cur = nxt;
        x0 = x0n; x1 = x1n;
    }

    g_hfinal[((b0       * E_N + e) * 2 + d) * H_N + lane] = h0v;
    g_hfinal[(((b0 + 1) * E_N + e) * 2 + d) * H_N + lane] = h1v;
}

// Per-batch epilogue: per-electrode LayerNorm over 64 features, mean over
// electrodes, then the 64->1 FC. One block per batch element, 64 threads.
__global__ void __launch_bounds__(64)
head_kernel(const float* __restrict__ ln_gamma,  // [E, 64]
            const float* __restrict__ ln_beta,   // [E, 64]
            const float* __restrict__ fc_w,      // [1, 64]
            const float* __restrict__ fc_b,      // [1]
            float* __restrict__ out)             // [B]
{
    const int b = blockIdx.x;
    const int f = threadIdx.x;   // feature = dir*32 + l
    __shared__ float red[4];
    const float* hb = g_hfinal + b * (E_N * 2 * H_N);

    float pooled = 0.f;
    for (int e = 0; e < E_N; e++) {
        float v = hb[e * 64 + f];
        float s = v, s2 = v * v;
#pragma unroll
        for (int off = 16; off; off >>= 1) {
            s  += __shfl_xor_sync(0xffffffffu, s,  off);
            s2 += __shfl_xor_sync(0xffffffffu, s2, off);
        }
        if ((f & 31) == 0) { red[(f >> 5) * 2] = s; red[(f >> 5) * 2 + 1] = s2; }
        __syncthreads();
        float S = red[0] + red[2], S2 = red[1] + red[3];
        __syncthreads();
        float mu  = S * (1.0f / 64.0f);
        float var = fmaf(-mu, mu, S2 * (1.0f / 64.0f));
        float nv  = (v - mu) * rsqrtf(var + 1e-5f);
        pooled += fmaf(nv, ln_gamma[e * 64 + f], ln_beta[e * 64 + f]);
    }
    pooled *= (1.0f / (float)E_N);

    float a = pooled * fc_w[f];
#pragma unroll
    for (int off = 16; off; off >>= 1) a += __shfl_xor_sync(0xffffffffu, a, off);
    if ((f & 31) == 0) red[f >> 5] = a;
    __syncthreads();
    if (f == 0) out[b] = red[0] + red[1] + fc_b[0];
}

extern "C" void kernel_launch(void* const* d_in, const int* in_sizes, int n_in,
                              void* d_out, int out_size) {
    const float* x        = (const float*)d_in[0];
    const float* w_ih     = (const float*)d_in[1];
    const float* w_hh     = (const float*)d_in[2];
    const float* b_ih     = (const float*)d_in[3];
    const float* b_hh     = (const float*)d_in[4];
    const float* ln_gamma = (const float*)d_in[5];
    const float* ln_beta  = (const float*)d_in[6];
    const float* fc_w     = (const float*)d_in[7];
    const float* fc_b     = (const float*)d_in[8];
    float* out = (float*)d_out;

    lstm_kernel<<<E_N * 2 * (B_N / 2), 32>>>(x, w_ih, w_hh, b_ih, b_hh);
    head_kernel<<<B_N, 64>>>(ln_gamma, ln_beta, fc_w, fc_b, out);
}